// round 6
// baseline (speedup 1.0000x reference)
#include <cuda_runtime.h>

#define BATCH 32
#define LSEQ  2048
#define DDIM  1024
#define NVOC  320
#define SPLIT 32
#define LSEG  (LSEQ / SPLIT)   // 64

// Scratch (allocation-free rule: __device__ globals)
__device__ float g_partial[SPLIT * BATCH * DDIM];   // 16 MB

// ---------------------------------------------------------------------------
// Fused kernel: every block (split, b) redundantly computes its batch's
// histogram + weight-sum (cheap, overlapped across 1024 resident blocks),
// then streams its 64-row feature segment with the weighted accumulation.
// Output partial is pre-normalized by 1/sum(p).
// vq_indices / input_lengths are int32 (JAX x64-disabled downcast).
// ---------------------------------------------------------------------------
#define JL (LSEQ / 256)   // 8 l-values per thread

__global__ void __launch_bounds__(256)
gemv_fused_kernel(const float* __restrict__ feat,
                  const int*   __restrict__ lengths,
                  const int*   __restrict__ vq)
{
    __shared__ int   s_cx[NVOC];
    __shared__ int   s_cy[NVOC];
    __shared__ float s_p[LSEQ];     // unnormalized per-position weights
    __shared__ float s_red[8];
    __shared__ float s_inv;

    const int split = blockIdx.x;   // 0..SPLIT-1
    const int b     = blockIdx.y;   // 0..BATCH-1
    const int tid   = threadIdx.x;  // 0..255

    // ---- Phase A: histogram (full batch, redundant per split) ----
    // NVOC=320 > blockDim=256: MUST stride (a predicated single write left
    // entries 256..319 stale on graph replays -> R5 post-timing divergence).
    for (int i = tid; i < NVOC; i += 256) { s_cx[i] = 0; s_cy[i] = 0; }
    __syncthreads();

    const int2* vq2 = reinterpret_cast<const int2*>(vq) + (size_t)b * LSEQ;
    int ix[JL], iy[JL];
#pragma unroll
    for (int j = 0; j < JL; j++) {
        int2 v = vq2[tid + j * 256];
        ix[j] = v.x;
        iy[j] = v.y;
        atomicAdd(&s_cx[ix[j]], 1);
        atomicAdd(&s_cy[iy[j]], 1);
    }
    __syncthreads();

    // ---- Phase B: per-position p = mask / freq, and block sum ----
    const int len = lengths[b];
    float lsum = 0.0f;
#pragma unroll
    for (int j = 0; j < JL; j++) {
        const int l = tid + j * 256;
        float p = 0.0f;
        if (l < len)
            p = __fdividef(1.0f, (float)(s_cx[ix[j]] + s_cy[iy[j]]));
        s_p[l] = p;
        lsum += p;
    }
#pragma unroll
    for (int o = 16; o > 0; o >>= 1) lsum += __shfl_xor_sync(0xffffffffu, lsum, o);
    if ((tid & 31) == 0) s_red[tid >> 5] = lsum;
    __syncthreads();
    if (tid < 8) {
        float s = s_red[tid];
#pragma unroll
        for (int o = 4; o > 0; o >>= 1) s += __shfl_xor_sync(0xffu, s, o);
        if (tid == 0) s_inv = __fdividef(1.0f, s);
    }
    __syncthreads();

    // ---- Phase C: stream the 64-row feature segment, weighted by p ----
    // feat slice: input_feature[b, 1, l, d]  (N=2, take last)
    const float4* f4 = reinterpret_cast<const float4*>(
        feat + ((size_t)b * 2 + 1) * (size_t)LSEQ * DDIM
             + (size_t)split * LSEG * DDIM) + tid;
    const float* pw = &s_p[split * LSEG];

    float4 acc = make_float4(0.f, 0.f, 0.f, 0.f);
#pragma unroll 16
    for (int l = 0; l < LSEG; l++) {
        const float  w = pw[l];
        const float4 v = __ldcs(f4 + (size_t)l * (DDIM / 4));
        acc.x = fmaf(w, v.x, acc.x);
        acc.y = fmaf(w, v.y, acc.y);
        acc.z = fmaf(w, v.z, acc.z);
        acc.w = fmaf(w, v.w, acc.w);
    }

    const float inv = s_inv;
    acc.x *= inv; acc.y *= inv; acc.z *= inv; acc.w *= inv;

    float4* out4 = reinterpret_cast<float4*>(
        &g_partial[((size_t)split * BATCH + b) * DDIM]);
    out4[tid] = acc;
}

// ---------------------------------------------------------------------------
// Reduce: fold SPLIT partials (already normalized) into the output.
// ---------------------------------------------------------------------------
__global__ void __launch_bounds__(256)
reduce_kernel(float* __restrict__ out)
{
    const int idx = blockIdx.x * 256 + threadIdx.x;  // float4 index, < B*D/4
    const float4* p = reinterpret_cast<const float4*>(g_partial);
    float4 acc = make_float4(0.f, 0.f, 0.f, 0.f);
#pragma unroll
    for (int s = 0; s < SPLIT; s++) {
        float4 v = p[(size_t)s * (BATCH * DDIM / 4) + idx];
        acc.x += v.x; acc.y += v.y; acc.z += v.z; acc.w += v.w;
    }
    reinterpret_cast<float4*>(out)[idx] = acc;
}

// ---------------------------------------------------------------------------
extern "C" void kernel_launch(void* const* d_in, const int* in_sizes, int n_in,
                              void* d_out, int out_size)
{
    const float* feat    = (const float*)d_in[0];
    const int*   lengths = (const int*)d_in[1];
    const int*   vq      = (const int*)d_in[2];
    float*       out     = (float*)d_out;

    (void)in_sizes; (void)n_in; (void)out_size;

    gemv_fused_kernel<<<dim3(SPLIT, BATCH), 256>>>(feat, lengths, vq);
    reduce_kernel<<<(BATCH * DDIM / 4) / 256, 256>>>(out);
}

// round 7
// speedup vs baseline: 1.0522x; 1.0522x over previous
#include <cuda_runtime.h>

#define BATCH 32
#define LSEQ  2048
#define DDIM  1024
#define NVOC  320
#define SPLIT 32
#define LSEG  (LSEQ / SPLIT)   // 64

// ---------------------------------------------------------------------------
// Fused kernel: every block (split, b) redundantly computes its batch's
// histogram + weight-sum (cheap, 1024 blocks resident across 148 SMs),
// streams its 64-row feature segment with weighted accumulation, and
// reduces its normalized partial straight into `out` via red.global.v4.f32.
// vq_indices / input_lengths are int32 (JAX x64-disabled downcast).
// ---------------------------------------------------------------------------
#define JL (LSEQ / 256)   // 8 l-values per thread

__global__ void __launch_bounds__(256)
gemv_fused_kernel(const float* __restrict__ feat,
                  const int*   __restrict__ lengths,
                  const int*   __restrict__ vq,
                  float*       __restrict__ out)
{
    __shared__ int   s_cx[NVOC];
    __shared__ int   s_cy[NVOC];
    __shared__ float s_p[LSEQ];     // unnormalized per-position weights
    __shared__ float s_red[8];
    __shared__ float s_inv;

    const int split = blockIdx.x;   // 0..SPLIT-1
    const int b     = blockIdx.y;   // 0..BATCH-1
    const int tid   = threadIdx.x;  // 0..255

    // ---- Phase A: histogram (full batch, redundant per split) ----
    // NVOC=320 > blockDim=256: MUST stride (R5 lesson: stale smem on replay).
    for (int i = tid; i < NVOC; i += 256) { s_cx[i] = 0; s_cy[i] = 0; }
    __syncthreads();

    const int2* vq2 = reinterpret_cast<const int2*>(vq) + (size_t)b * LSEQ;
    int ix[JL], iy[JL];
#pragma unroll
    for (int j = 0; j < JL; j++) {
        int2 v = vq2[tid + j * 256];
        ix[j] = v.x;
        iy[j] = v.y;
        atomicAdd(&s_cx[ix[j]], 1);
        atomicAdd(&s_cy[iy[j]], 1);
    }
    __syncthreads();

    // ---- Phase B: per-position p = mask / freq, block sum -> 1/sum ----
    const int len = lengths[b];
    float lsum = 0.0f;
#pragma unroll
    for (int j = 0; j < JL; j++) {
        const int l = tid + j * 256;
        float p = 0.0f;
        if (l < len)
            p = __fdividef(1.0f, (float)(s_cx[ix[j]] + s_cy[iy[j]]));
        s_p[l] = p;
        lsum += p;
    }
#pragma unroll
    for (int o = 16; o > 0; o >>= 1) lsum += __shfl_xor_sync(0xffffffffu, lsum, o);
    if ((tid & 31) == 0) s_red[tid >> 5] = lsum;
    __syncthreads();
    if (tid < 8) {
        float s = s_red[tid];
#pragma unroll
        for (int o = 4; o > 0; o >>= 1) s += __shfl_xor_sync(0xffu, s, o);
        if (tid == 0) s_inv = __fdividef(1.0f, s);
    }
    __syncthreads();

    // ---- Phase C: stream the 64-row feature segment, weighted by p ----
    // feat slice: input_feature[b, 1, l, d]  (N=2, take last)
    const float4* f4 = reinterpret_cast<const float4*>(
        feat + ((size_t)b * 2 + 1) * (size_t)LSEQ * DDIM
             + (size_t)split * LSEG * DDIM) + tid;
    const float* pw = &s_p[split * LSEG];

    float4 acc = make_float4(0.f, 0.f, 0.f, 0.f);
#pragma unroll 16
    for (int l = 0; l < LSEG; l++) {
        const float  w = pw[l];
        const float4 v = __ldcs(f4 + (size_t)l * (DDIM / 4));
        acc.x = fmaf(w, v.x, acc.x);
        acc.y = fmaf(w, v.y, acc.y);
        acc.z = fmaf(w, v.z, acc.z);
        acc.w = fmaf(w, v.w, acc.w);
    }

    const float inv = s_inv;
    acc.x *= inv; acc.y *= inv; acc.z *= inv; acc.w *= inv;

    // ---- Phase D: vector reduction straight into the output ----
    float* dst = out + (size_t)b * DDIM + tid * 4;
    asm volatile("red.global.add.v4.f32 [%0], {%1, %2, %3, %4};"
                 :: "l"(dst), "f"(acc.x), "f"(acc.y), "f"(acc.z), "f"(acc.w)
                 : "memory");
}

// ---------------------------------------------------------------------------
extern "C" void kernel_launch(void* const* d_in, const int* in_sizes, int n_in,
                              void* d_out, int out_size)
{
    const float* feat    = (const float*)d_in[0];
    const int*   lengths = (const int*)d_in[1];
    const int*   vq      = (const int*)d_in[2];
    float*       out     = (float*)d_out;

    (void)in_sizes; (void)n_in;

    // Output is poisoned before timing and accumulated via atomics: zero it.
    cudaMemsetAsync(out, 0, (size_t)out_size * sizeof(float));
    gemv_fused_kernel<<<dim3(SPLIT, BATCH), 256>>>(feat, lengths, vq, out);
}

// round 8
// speedup vs baseline: 1.1894x; 1.1304x over previous
#include <cuda_runtime.h>

#define BATCH 32
#define LSEQ  2048
#define DDIM  1024
#define NVOC  320
#define SPLIT 32
#define LSEG  (LSEQ / SPLIT)   // 64

// ---------------------------------------------------------------------------
// Fused kernel: per-(split,b) block redundantly computes its batch's
// histogram + weight-sum, streams its 64-row feature segment, and reduces
// its normalized partial straight into `out` via red.global.v4.f32.
// L2 prefetch of the first 24 rows hides the prologue's HBM dead time.
// vq_indices / input_lengths are int32 (JAX x64-disabled downcast).
// ---------------------------------------------------------------------------
#define JL      (LSEQ / 256)   // 8 l-values per thread
#define PF_LINES 3             // 3 x 128B lines/thread = rows 0..23 of segment

__global__ void __launch_bounds__(256)
gemv_fused_kernel(const float* __restrict__ feat,
                  const int*   __restrict__ lengths,
                  const int*   __restrict__ vq,
                  float*       __restrict__ out)
{
    __shared__ int   s_cx[NVOC];
    __shared__ int   s_cy[NVOC];
    __shared__ float s_p[LSEQ];     // unnormalized per-position weights
    __shared__ float s_red[8];
    __shared__ float s_inv;

    const int split = blockIdx.x;   // 0..SPLIT-1
    const int b     = blockIdx.y;   // 0..BATCH-1
    const int tid   = threadIdx.x;  // 0..255

    // Segment base: input_feature[b, 1, split*LSEG, :]  (N=2, take last)
    const float* seg = feat + ((size_t)b * 2 + 1) * (size_t)LSEQ * DDIM
                            + (size_t)split * LSEG * DDIM;

    // ---- Phase 0: L2 prefetch of rows 0..23 (96 KB/block) -----------------
    // Distinct 128B lines per thread: fires while the prologue computes.
    {
        const char* pf = reinterpret_cast<const char*>(seg) + (size_t)tid * 128;
#pragma unroll
        for (int i = 0; i < PF_LINES; i++)
            asm volatile("prefetch.global.L2 [%0];"
                         :: "l"(pf + (size_t)i * 256 * 128) : "memory");
    }

    // ---- Phase A: histogram (full batch, redundant per split) ----
    // NVOC=320 > blockDim=256: MUST stride (R5 lesson: stale smem on replay).
    for (int i = tid; i < NVOC; i += 256) { s_cx[i] = 0; s_cy[i] = 0; }
    __syncthreads();

    const int2* vq2 = reinterpret_cast<const int2*>(vq) + (size_t)b * LSEQ;
    int ix[JL], iy[JL];
#pragma unroll
    for (int j = 0; j < JL; j++) {
        int2 v = vq2[tid + j * 256];
        ix[j] = v.x;
        iy[j] = v.y;
        atomicAdd(&s_cx[ix[j]], 1);
        atomicAdd(&s_cy[iy[j]], 1);
    }
    __syncthreads();

    // ---- Phase B: per-position p = mask / freq, block sum -> 1/sum ----
    const int len = lengths[b];
    float lsum = 0.0f;
#pragma unroll
    for (int j = 0; j < JL; j++) {
        const int l = tid + j * 256;
        float p = 0.0f;
        if (l < len)
            p = __fdividef(1.0f, (float)(s_cx[ix[j]] + s_cy[iy[j]]));
        s_p[l] = p;
        lsum += p;
    }
#pragma unroll
    for (int o = 16; o > 0; o >>= 1) lsum += __shfl_xor_sync(0xffffffffu, lsum, o);
    if ((tid & 31) == 0) s_red[tid >> 5] = lsum;
    __syncthreads();
    if (tid < 8) {
        float s = s_red[tid];
#pragma unroll
        for (int o = 4; o > 0; o >>= 1) s += __shfl_xor_sync(0xffu, s, o);
        if (tid == 0) s_inv = __fdividef(1.0f, s);
    }
    __syncthreads();

    // ---- Phase C: stream the 64-row feature segment, weighted by p ----
    const float4* f4 = reinterpret_cast<const float4*>(seg) + tid;
    const float*  pw = &s_p[split * LSEG];

    float4 acc = make_float4(0.f, 0.f, 0.f, 0.f);
#pragma unroll 16
    for (int l = 0; l < LSEG; l++) {
        const float  w = pw[l];
        const float4 v = __ldcs(f4 + (size_t)l * (DDIM / 4));
        acc.x = fmaf(w, v.x, acc.x);
        acc.y = fmaf(w, v.y, acc.y);
        acc.z = fmaf(w, v.z, acc.z);
        acc.w = fmaf(w, v.w, acc.w);
    }

    const float inv = s_inv;
    acc.x *= inv; acc.y *= inv; acc.z *= inv; acc.w *= inv;

    // ---- Phase D: vector reduction straight into the output ----
    float* dst = out + (size_t)b * DDIM + tid * 4;
    asm volatile("red.global.add.v4.f32 [%0], {%1, %2, %3, %4};"
                 :: "l"(dst), "f"(acc.x), "f"(acc.y), "f"(acc.z), "f"(acc.w)
                 : "memory");
}

// ---------------------------------------------------------------------------
extern "C" void kernel_launch(void* const* d_in, const int* in_sizes, int n_in,
                              void* d_out, int out_size)
{
    const float* feat    = (const float*)d_in[0];
    const int*   lengths = (const int*)d_in[1];
    const int*   vq      = (const int*)d_in[2];
    float*       out     = (float*)d_out;

    (void)in_sizes; (void)n_in;

    // Output is poisoned before timing and accumulated via atomics: zero it.
    cudaMemsetAsync(out, 0, (size_t)out_size * sizeof(float));
    gemv_fused_kernel<<<dim3(SPLIT, BATCH), 256>>>(feat, lengths, vq, out);
}